// round 3
// baseline (speedup 1.0000x reference)
#include <cuda_runtime.h>

#define NN 100000
#define NE 1000000
#define HD 64
#define NC 16
#define TILE 64
#define PX 68          // padded smem pitch (floats) for [k][n] tiles: conflict-free + float4 aligned
#define NTILES ((NN + TILE - 1) / TILE)

// Scratch (allocation-free rule: __device__ globals)
__device__ float g_agg0[(size_t)NN * HD];   // sum of src features over type==true edges, per dst
__device__ float g_agg1[(size_t)NN * HD];   // type==false
__device__ float g_cnt0[NN];
__device__ float g_cnt1[NN];

// ---------------------------------------------------------------------------
// Edge phase: 16 threads per edge, each thread handles one float4 (64 floats).
// Vector atomics (red.global.add.v4.f32) -> 4x fewer REDG ops.
// ---------------------------------------------------------------------------
__global__ void __launch_bounds__(256) edge_kernel(
    const float* __restrict__ feat,
    const int* __restrict__ src,
    const int* __restrict__ dst,
    const int* __restrict__ et)
{
    int e = blockIdx.x * 16 + (threadIdx.x >> 4);
    if (e >= NE) return;
    int l = threadIdx.x & 15;
    int s = __ldg(src + e);
    int d = __ldg(dst + e);
    int t = __ldg(et + e);
    float4 v = *reinterpret_cast<const float4*>(feat + (size_t)s * HD + l * 4);
    float* p = (t ? g_agg0 : g_agg1) + (size_t)d * HD + l * 4;
    asm volatile("red.global.add.v4.f32 [%0], {%1,%2,%3,%4};"
                 :: "l"(p), "f"(v.x), "f"(v.y), "f"(v.z), "f"(v.w)
                 : "memory");
    if (l == 0) atomicAdd((t ? g_cnt0 : g_cnt1) + d, 1.0f);
}

__device__ __forceinline__ float sigmoidf_(float x) {
    return 1.0f / (1.0f + __expf(-x));
}
__device__ __forceinline__ float tanhf_(float x) {
    return 2.0f / (1.0f + __expf(-2.0f * x)) - 1.0f;
}

// ---------------------------------------------------------------------------
// Node phase. One block = 256 threads, tiles of 64 nodes, weights in smem.
// Thread (ns = tid&15, js = tid>>4) owns a 4-node x 4-output register tile.
// GEMM1: pre = agg0@W0^T + agg1@W1^T + cnt0*b0 + cnt1*b1     -> Pre^T in XA
// GEMM2: ALL 3 GRU gates fused in one k-loop:
//   aR = pre@Wih_r^T + feat@Whh_r^T   (merged accumulator)
//   aZ = pre@Wih_z^T + feat@Whh_z^T   (merged accumulator)
//   aI = pre@Wih_n^T,  aH = feat@Whh_n^T  (kept separate for r*h_n)
//   8 LDS.128 per k for 96 FMAs (was 12 LDS / 96 FMA over 3 passes)
// GEMM3: out = h@Wout^T + bout
// ---------------------------------------------------------------------------
__global__ void __launch_bounds__(256, 1) node_kernel(
    const float* __restrict__ feat,
    const float* __restrict__ W0g, const float* __restrict__ b0g,
    const float* __restrict__ W1g, const float* __restrict__ b1g,
    const float* __restrict__ Wihg, const float* __restrict__ Whhg,
    const float* __restrict__ bihg, const float* __restrict__ bhhg,
    const float* __restrict__ Woutg, const float* __restrict__ boutg,
    float* __restrict__ out)
{
    extern __shared__ float sm[];
    float* W0s = sm;                  // [64k][64j]
    float* W1s = W0s + 4096;
    float* WIs = W1s + 4096;          // [64k][192j]
    float* WHs = WIs + 12288;
    float* WOs = WHs + 12288;         // [64k][16c]
    float* B0s = WOs + 1024;
    float* B1s = B0s + 64;
    float* BIs = B1s + 64;
    float* BHs = BIs + 192;
    float* BOs = BHs + 192;
    float* XA  = BOs + 16;            // [64k][PX]
    float* XB  = XA + TILE * PX;
    float* XF  = XB + TILE * PX;
    float* C0s = XF + TILE * PX;
    float* C1s = C0s + 64;

    const int tid = threadIdx.x;

    // --- Load weights transposed (k-major). One-time cost per block. ---
    for (int i = tid; i < 4096; i += 256) {
        int j = i & 63, k = i >> 6;
        W0s[k * 64 + j] = W0g[j * 64 + k];
        W1s[k * 64 + j] = W1g[j * 64 + k];
    }
    for (int i = tid; i < 12288; i += 256) {
        int j = i % 192, k = i / 192;
        WIs[k * 192 + j] = Wihg[j * 64 + k];
        WHs[k * 192 + j] = Whhg[j * 64 + k];
    }
    for (int i = tid; i < 1024; i += 256) {
        int c = i & 15, k = i >> 4;
        WOs[k * 16 + c] = Woutg[c * 64 + k];
    }
    if (tid < 64)  { B0s[tid] = b0g[tid]; B1s[tid] = b1g[tid]; }
    if (tid < 192) { BIs[tid] = bihg[tid]; BHs[tid] = bhhg[tid]; }
    if (tid < 16)  { BOs[tid] = boutg[tid]; }

    const int ns = tid & 15;   // node slot: nodes 4*ns .. 4*ns+3
    const int js = tid >> 4;   // output slot: outputs 4*js .. 4*js+3 (and c=js in GEMM3)

    for (int tile = blockIdx.x; tile < NTILES; tile += gridDim.x) {
        __syncthreads();  // covers weight load (1st iter) + prev-tile buffer reads
        const int base = tile * TILE;

        // --- Stage agg0/agg1/feat transposed into smem ([k][n], pitch PX). ---
        for (int i = tid; i < TILE * 16; i += 256) {
            int k4 = i >> 6, n = i & 63;
            int gn = base + n;
            float4 a0, a1, f;
            if (gn < NN) {
                a0 = *reinterpret_cast<const float4*>(g_agg0 + (size_t)gn * HD + k4 * 4);
                a1 = *reinterpret_cast<const float4*>(g_agg1 + (size_t)gn * HD + k4 * 4);
                f  = *reinterpret_cast<const float4*>(feat   + (size_t)gn * HD + k4 * 4);
            } else {
                a0 = make_float4(0.f, 0.f, 0.f, 0.f); a1 = a0; f = a0;
            }
            int kb = 4 * k4;
            XA[(kb + 0) * PX + n] = a0.x; XA[(kb + 1) * PX + n] = a0.y;
            XA[(kb + 2) * PX + n] = a0.z; XA[(kb + 3) * PX + n] = a0.w;
            XB[(kb + 0) * PX + n] = a1.x; XB[(kb + 1) * PX + n] = a1.y;
            XB[(kb + 2) * PX + n] = a1.z; XB[(kb + 3) * PX + n] = a1.w;
            XF[(kb + 0) * PX + n] = f.x;  XF[(kb + 1) * PX + n] = f.y;
            XF[(kb + 2) * PX + n] = f.z;  XF[(kb + 3) * PX + n] = f.w;
        }
        if (tid < TILE) {
            int gn = base + tid;
            C0s[tid] = (gn < NN) ? g_cnt0[gn] : 0.0f;
            C1s[tid] = (gn < NN) ? g_cnt1[gn] : 0.0f;
        }
        __syncthreads();

        // --- GEMM1: pre[n][j] ---
        float acc[4][4];
        #pragma unroll
        for (int q = 0; q < 4; q++)
            #pragma unroll
            for (int p = 0; p < 4; p++) acc[q][p] = 0.0f;

        #pragma unroll 8
        for (int k = 0; k < 64; k++) {
            float4 x0 = *reinterpret_cast<const float4*>(XA + k * PX + 4 * ns);
            float4 x1 = *reinterpret_cast<const float4*>(XB + k * PX + 4 * ns);
            float4 w0 = *reinterpret_cast<const float4*>(W0s + k * 64 + 4 * js);
            float4 w1 = *reinterpret_cast<const float4*>(W1s + k * 64 + 4 * js);
            const float xq0[4] = {x0.x, x0.y, x0.z, x0.w};
            const float xq1[4] = {x1.x, x1.y, x1.z, x1.w};
            const float wp0[4] = {w0.x, w0.y, w0.z, w0.w};
            const float wp1[4] = {w1.x, w1.y, w1.z, w1.w};
            #pragma unroll
            for (int q = 0; q < 4; q++)
                #pragma unroll
                for (int p = 0; p < 4; p++)
                    acc[q][p] += xq0[q] * wp0[p] + xq1[q] * wp1[p];
        }
        {
            float4 b0v = *reinterpret_cast<const float4*>(B0s + 4 * js);
            float4 b1v = *reinterpret_cast<const float4*>(B1s + 4 * js);
            const float b0p[4] = {b0v.x, b0v.y, b0v.z, b0v.w};
            const float b1p[4] = {b1v.x, b1v.y, b1v.z, b1v.w};
            #pragma unroll
            for (int q = 0; q < 4; q++) {
                float c0 = C0s[4 * ns + q], c1 = C1s[4 * ns + q];
                #pragma unroll
                for (int p = 0; p < 4; p++)
                    acc[q][p] += c0 * b0p[p] + c1 * b1p[p];
            }
        }
        __syncthreads();   // everyone done reading XA/XB as inputs
        // store Pre^T into XA (aliases dead agg0 tile)
        #pragma unroll
        for (int p = 0; p < 4; p++) {
            *reinterpret_cast<float4*>(XA + (4 * js + p) * PX + 4 * ns) =
                make_float4(acc[0][p], acc[1][p], acc[2][p], acc[3][p]);
        }
        __syncthreads();

        // --- GEMM2: all 3 gates in ONE k-loop (x-loads amortized 3x) ---
        float aR[4][4], aZ[4][4], aI[4][4], aH[4][4];
        #pragma unroll
        for (int q = 0; q < 4; q++)
            #pragma unroll
            for (int p = 0; p < 4; p++) {
                aR[q][p] = 0.0f; aZ[q][p] = 0.0f;
                aI[q][p] = 0.0f; aH[q][p] = 0.0f;
            }

        #pragma unroll 4
        for (int k = 0; k < 64; k++) {
            float4 pv  = *reinterpret_cast<const float4*>(XA + k * PX + 4 * ns);
            float4 fv  = *reinterpret_cast<const float4*>(XF + k * PX + 4 * ns);
            float4 wir = *reinterpret_cast<const float4*>(WIs + k * 192 +   0 + 4 * js);
            float4 whr = *reinterpret_cast<const float4*>(WHs + k * 192 +   0 + 4 * js);
            float4 wiz = *reinterpret_cast<const float4*>(WIs + k * 192 +  64 + 4 * js);
            float4 whz = *reinterpret_cast<const float4*>(WHs + k * 192 +  64 + 4 * js);
            float4 win = *reinterpret_cast<const float4*>(WIs + k * 192 + 128 + 4 * js);
            float4 whn = *reinterpret_cast<const float4*>(WHs + k * 192 + 128 + 4 * js);
            const float pq[4]  = {pv.x, pv.y, pv.z, pv.w};
            const float fq[4]  = {fv.x, fv.y, fv.z, fv.w};
            const float irp[4] = {wir.x, wir.y, wir.z, wir.w};
            const float hrp[4] = {whr.x, whr.y, whr.z, whr.w};
            const float izp[4] = {wiz.x, wiz.y, wiz.z, wiz.w};
            const float hzp[4] = {whz.x, whz.y, whz.z, whz.w};
            const float inp[4] = {win.x, win.y, win.z, win.w};
            const float hnp[4] = {whn.x, whn.y, whn.z, whn.w};
            #pragma unroll
            for (int q = 0; q < 4; q++)
                #pragma unroll
                for (int p = 0; p < 4; p++) {
                    aR[q][p] += pq[q] * irp[p] + fq[q] * hrp[p];
                    aZ[q][p] += pq[q] * izp[p] + fq[q] * hzp[p];
                    aI[q][p] += pq[q] * inp[p];
                    aH[q][p] += fq[q] * hnp[p];
                }
        }

        // --- GRU elementwise epilogue ---
        {
            float4 birv = *reinterpret_cast<const float4*>(BIs +   0 + 4 * js);
            float4 bhrv = *reinterpret_cast<const float4*>(BHs +   0 + 4 * js);
            float4 bizv = *reinterpret_cast<const float4*>(BIs +  64 + 4 * js);
            float4 bhzv = *reinterpret_cast<const float4*>(BHs +  64 + 4 * js);
            float4 binv = *reinterpret_cast<const float4*>(BIs + 128 + 4 * js);
            float4 bhnv = *reinterpret_cast<const float4*>(BHs + 128 + 4 * js);
            const float brp[4] = {birv.x + bhrv.x, birv.y + bhrv.y, birv.z + bhrv.z, birv.w + bhrv.w};
            const float bzp[4] = {bizv.x + bhzv.x, bizv.y + bhzv.y, bizv.z + bhzv.z, bizv.w + bhzv.w};
            const float bip[4] = {binv.x, binv.y, binv.z, binv.w};
            const float bhp[4] = {bhnv.x, bhnv.y, bhnv.z, bhnv.w};
            #pragma unroll
            for (int p = 0; p < 4; p++) {
                float hq[4];
                #pragma unroll
                for (int q = 0; q < 4; q++) {
                    float r  = sigmoidf_(aR[q][p] + brp[p]);
                    float z  = sigmoidf_(aZ[q][p] + bzp[p]);
                    float nn = tanhf_(aI[q][p] + bip[p] + r * (aH[q][p] + bhp[p]));
                    float fv2 = XF[(4 * js + p) * PX + 4 * ns + q];
                    hq[q] = (1.0f - z) * nn + z * fv2;
                }
                // store H^T into XB (aliases dead agg1 tile)
                *reinterpret_cast<float4*>(XB + (4 * js + p) * PX + 4 * ns) =
                    make_float4(hq[0], hq[1], hq[2], hq[3]);
            }
        }
        __syncthreads();

        // --- GEMM3: out[n][c], c = js ---
        float o[4] = {0.f, 0.f, 0.f, 0.f};
        #pragma unroll 8
        for (int k = 0; k < 64; k++) {
            float4 h4 = *reinterpret_cast<const float4*>(XB + k * PX + 4 * ns);
            float w = WOs[k * 16 + js];
            o[0] += h4.x * w; o[1] += h4.y * w; o[2] += h4.z * w; o[3] += h4.w * w;
        }
        float bo = BOs[js];
        #pragma unroll
        for (int q = 0; q < 4; q++) {
            int gn = base + 4 * ns + q;
            if (gn < NN) out[(size_t)gn * NC + js] = o[q] + bo;
        }
    }
}

// ---------------------------------------------------------------------------
extern "C" void kernel_launch(void* const* d_in, const int* in_sizes, int n_in,
                              void* d_out, int out_size)
{
    const float* feat = (const float*)d_in[0];
    const int*   src  = (const int*)d_in[1];
    const int*   dst  = (const int*)d_in[2];
    const int*   et   = (const int*)d_in[3];
    const float* W0   = (const float*)d_in[4];
    const float* b0   = (const float*)d_in[5];
    const float* W1   = (const float*)d_in[6];
    const float* b1   = (const float*)d_in[7];
    const float* Wih  = (const float*)d_in[8];
    const float* Whh  = (const float*)d_in[9];
    const float* bih  = (const float*)d_in[10];
    const float* bhh  = (const float*)d_in[11];
    const float* Wout = (const float*)d_in[12];
    const float* bout = (const float*)d_in[13];
    float* out = (float*)d_out;

    void *p0, *p1, *p2, *p3;
    cudaGetSymbolAddress(&p0, g_agg0);
    cudaGetSymbolAddress(&p1, g_agg1);
    cudaGetSymbolAddress(&p2, g_cnt0);
    cudaGetSymbolAddress(&p3, g_cnt1);
    cudaMemsetAsync(p0, 0, sizeof(float) * (size_t)NN * HD);
    cudaMemsetAsync(p1, 0, sizeof(float) * (size_t)NN * HD);
    cudaMemsetAsync(p2, 0, sizeof(float) * NN);
    cudaMemsetAsync(p3, 0, sizeof(float) * NN);

    edge_kernel<<<(NE + 15) / 16, 256>>>(feat, src, dst, et);

    const int SMEM_BYTES = 47504 * 4;  // 190016 B
    cudaFuncSetAttribute(node_kernel,
                         cudaFuncAttributeMaxDynamicSharedMemorySize, SMEM_BYTES);
    node_kernel<<<148, 256, SMEM_BYTES>>>(feat, W0, b0, W1, b1,
                                          Wih, Whh, bih, bhh, Wout, bout, out);
}

// round 4
// speedup vs baseline: 1.1342x; 1.1342x over previous
#include <cuda_runtime.h>

#define NN 100000
#define NE 1000000
#define HD 64
#define NC 16
#define TILE 64
#define PX 68          // padded smem pitch (floats): conflict-free + 16B-aligned rows
#define NTILES ((NN + TILE - 1) / TILE)

// Scratch (allocation-free rule: __device__ globals)
__device__ float g_agg0[(size_t)NN * HD];
__device__ float g_agg1[(size_t)NN * HD];
__device__ float g_cnt0[NN];
__device__ float g_cnt1[NN];

// ---------------------------------------------------------------------------
// Packed f32x2 helpers (Blackwell fp32x2 path — ptxas never emits FFMA2 from C++)
// ---------------------------------------------------------------------------
typedef unsigned long long u64t;

__device__ __forceinline__ u64t splat2(float x) {
    u64t r;
    asm("mov.b64 %0, {%1, %1};" : "=l"(r) : "f"(x));
    return r;
}
__device__ __forceinline__ void fma2(u64t& d, u64t a, u64t b) {
    asm("fma.rn.f32x2 %0, %1, %2, %0;" : "+l"(d) : "l"(a), "l"(b));
}
__device__ __forceinline__ float2 unpk(u64t v) {
    float2 f;
    asm("mov.b64 {%0, %1}, %2;" : "=f"(f.x), "=f"(f.y) : "l"(v));
    return f;
}

// ---------------------------------------------------------------------------
// Edge phase: 16 threads per edge, one float4 each; red.global.add.v4.f32.
// ---------------------------------------------------------------------------
__global__ void __launch_bounds__(256) edge_kernel(
    const float* __restrict__ feat,
    const int* __restrict__ src,
    const int* __restrict__ dst,
    const int* __restrict__ et)
{
    int e = blockIdx.x * 16 + (threadIdx.x >> 4);
    if (e >= NE) return;
    int l = threadIdx.x & 15;
    int s = __ldg(src + e);
    int d = __ldg(dst + e);
    int t = __ldg(et + e);
    float4 v = *reinterpret_cast<const float4*>(feat + (size_t)s * HD + l * 4);
    float* p = (t ? g_agg0 : g_agg1) + (size_t)d * HD + l * 4;
    asm volatile("red.global.add.v4.f32 [%0], {%1,%2,%3,%4};"
                 :: "l"(p), "f"(v.x), "f"(v.y), "f"(v.z), "f"(v.w)
                 : "memory");
    if (l == 0) atomicAdd((t ? g_cnt0 : g_cnt1) + d, 1.0f);
}

__device__ __forceinline__ float sigmoidf_(float x) {
    return 1.0f / (1.0f + __expf(-x));
}
__device__ __forceinline__ float tanhf_(float x) {
    return 2.0f / (1.0f + __expf(-2.0f * x)) - 1.0f;
}

// ---------------------------------------------------------------------------
// Node phase. 256 threads/block, 64-node tiles, all weights smem-resident.
// Thread (ns = tid&15, js = tid>>4) owns a 4-node x 4-output register tile,
// with the output (p) dimension packed into f32x2 pairs.
// ---------------------------------------------------------------------------
__global__ void __launch_bounds__(256, 1) node_kernel(
    const float* __restrict__ feat,
    const float* __restrict__ W0g, const float* __restrict__ b0g,
    const float* __restrict__ W1g, const float* __restrict__ b1g,
    const float* __restrict__ Wihg, const float* __restrict__ Whhg,
    const float* __restrict__ bihg, const float* __restrict__ bhhg,
    const float* __restrict__ Woutg, const float* __restrict__ boutg,
    float* __restrict__ out)
{
    extern __shared__ float sm[];
    float* W0s = sm;                  // [64k][64j]
    float* W1s = W0s + 4096;
    float* WIs = W1s + 4096;          // [64k][192j]
    float* WHs = WIs + 12288;
    float* WOs = WHs + 12288;         // [64k][16c]
    float* B0s = WOs + 1024;
    float* B1s = B0s + 64;
    float* BIs = B1s + 64;
    float* BHs = BIs + 192;
    float* BOs = BHs + 192;
    float* XA  = BOs + 16;            // [64k][PX]
    float* XB  = XA + TILE * PX;
    float* XF  = XB + TILE * PX;
    float* C0s = XF + TILE * PX;
    float* C1s = C0s + 64;

    const int tid = threadIdx.x;

    // --- Load weights transposed (k-major). One-time cost per block. ---
    for (int i = tid; i < 4096; i += 256) {
        int j = i & 63, k = i >> 6;
        W0s[k * 64 + j] = W0g[j * 64 + k];
        W1s[k * 64 + j] = W1g[j * 64 + k];
    }
    for (int i = tid; i < 12288; i += 256) {
        int j = i % 192, k = i / 192;
        WIs[k * 192 + j] = Wihg[j * 64 + k];
        WHs[k * 192 + j] = Whhg[j * 64 + k];
    }
    for (int i = tid; i < 1024; i += 256) {
        int c = i & 15, k = i >> 4;
        WOs[k * 16 + c] = Woutg[c * 64 + k];
    }
    if (tid < 64)  { B0s[tid] = b0g[tid]; B1s[tid] = b1g[tid]; }
    if (tid < 192) { BIs[tid] = bihg[tid]; BHs[tid] = bhhg[tid]; }
    if (tid < 16)  { BOs[tid] = boutg[tid]; }

    const int ns = tid & 15;   // node slot: nodes 4*ns .. 4*ns+3
    const int js = tid >> 4;   // output slot: outputs 4*js .. 4*js+3 (and c=js in GEMM3)

    for (int tile = blockIdx.x; tile < NTILES; tile += gridDim.x) {
        __syncthreads();  // covers weight load (1st iter) + prev-tile buffer reads
        const int base = tile * TILE;

        // --- Stage agg0/agg1/feat transposed into smem ([k][n], pitch PX). ---
        for (int i = tid; i < TILE * 16; i += 256) {
            int k4 = i >> 6, n = i & 63;
            int gn = base + n;
            float4 a0, a1, f;
            if (gn < NN) {
                a0 = *reinterpret_cast<const float4*>(g_agg0 + (size_t)gn * HD + k4 * 4);
                a1 = *reinterpret_cast<const float4*>(g_agg1 + (size_t)gn * HD + k4 * 4);
                f  = *reinterpret_cast<const float4*>(feat   + (size_t)gn * HD + k4 * 4);
            } else {
                a0 = make_float4(0.f, 0.f, 0.f, 0.f); a1 = a0; f = a0;
            }
            int kb = 4 * k4;
            XA[(kb + 0) * PX + n] = a0.x; XA[(kb + 1) * PX + n] = a0.y;
            XA[(kb + 2) * PX + n] = a0.z; XA[(kb + 3) * PX + n] = a0.w;
            XB[(kb + 0) * PX + n] = a1.x; XB[(kb + 1) * PX + n] = a1.y;
            XB[(kb + 2) * PX + n] = a1.z; XB[(kb + 3) * PX + n] = a1.w;
            XF[(kb + 0) * PX + n] = f.x;  XF[(kb + 1) * PX + n] = f.y;
            XF[(kb + 2) * PX + n] = f.z;  XF[(kb + 3) * PX + n] = f.w;
        }
        if (tid < TILE) {
            int gn = base + tid;
            C0s[tid] = (gn < NN) ? g_cnt0[gn] : 0.0f;
            C1s[tid] = (gn < NN) ? g_cnt1[gn] : 0.0f;
        }
        __syncthreads();

        // --- GEMM1 (packed): pre[n][j],  acc2[q][p2] = f32x2 over p pair ---
        u64t acc2[4][2];
        #pragma unroll
        for (int q = 0; q < 4; q++) { acc2[q][0] = 0ULL; acc2[q][1] = 0ULL; }

        #pragma unroll 8
        for (int k = 0; k < 64; k++) {
            float4 x0 = *reinterpret_cast<const float4*>(XA + k * PX + 4 * ns);
            float4 x1 = *reinterpret_cast<const float4*>(XB + k * PX + 4 * ns);
            ulonglong2 w0 = *reinterpret_cast<const ulonglong2*>(W0s + k * 64 + 4 * js);
            ulonglong2 w1 = *reinterpret_cast<const ulonglong2*>(W1s + k * 64 + 4 * js);
            u64t xs0[4] = {splat2(x0.x), splat2(x0.y), splat2(x0.z), splat2(x0.w)};
            u64t xs1[4] = {splat2(x1.x), splat2(x1.y), splat2(x1.z), splat2(x1.w)};
            #pragma unroll
            for (int q = 0; q < 4; q++) {
                fma2(acc2[q][0], xs0[q], w0.x);
                fma2(acc2[q][1], xs0[q], w0.y);
                fma2(acc2[q][0], xs1[q], w1.x);
                fma2(acc2[q][1], xs1[q], w1.y);
            }
        }
        {
            ulonglong2 b0v = *reinterpret_cast<const ulonglong2*>(B0s + 4 * js);
            ulonglong2 b1v = *reinterpret_cast<const ulonglong2*>(B1s + 4 * js);
            #pragma unroll
            for (int q = 0; q < 4; q++) {
                u64t c0 = splat2(C0s[4 * ns + q]);
                u64t c1 = splat2(C1s[4 * ns + q]);
                fma2(acc2[q][0], c0, b0v.x);
                fma2(acc2[q][1], c0, b0v.y);
                fma2(acc2[q][0], c1, b1v.x);
                fma2(acc2[q][1], c1, b1v.y);
            }
        }
        __syncthreads();   // everyone done reading XA/XB as inputs
        // store Pre^T into XA (aliases dead agg0 tile)
        {
            float accs[4][4];
            #pragma unroll
            for (int q = 0; q < 4; q++) {
                float2 lo = unpk(acc2[q][0]);
                float2 hi = unpk(acc2[q][1]);
                accs[q][0] = lo.x; accs[q][1] = lo.y;
                accs[q][2] = hi.x; accs[q][3] = hi.y;
            }
            #pragma unroll
            for (int p = 0; p < 4; p++) {
                *reinterpret_cast<float4*>(XA + (4 * js + p) * PX + 4 * ns) =
                    make_float4(accs[0][p], accs[1][p], accs[2][p], accs[3][p]);
            }
        }
        __syncthreads();

        // --- GEMM2 (packed): all 3 gates in ONE k-loop ---
        u64t aR2[4][2], aZ2[4][2], aI2[4][2], aH2[4][2];
        #pragma unroll
        for (int q = 0; q < 4; q++) {
            aR2[q][0] = aR2[q][1] = 0ULL;
            aZ2[q][0] = aZ2[q][1] = 0ULL;
            aI2[q][0] = aI2[q][1] = 0ULL;
            aH2[q][0] = aH2[q][1] = 0ULL;
        }

        #pragma unroll 4
        for (int k = 0; k < 64; k++) {
            float4 pv = *reinterpret_cast<const float4*>(XA + k * PX + 4 * ns);
            float4 fv = *reinterpret_cast<const float4*>(XF + k * PX + 4 * ns);
            ulonglong2 wir = *reinterpret_cast<const ulonglong2*>(WIs + k * 192 +   0 + 4 * js);
            ulonglong2 whr = *reinterpret_cast<const ulonglong2*>(WHs + k * 192 +   0 + 4 * js);
            ulonglong2 wiz = *reinterpret_cast<const ulonglong2*>(WIs + k * 192 +  64 + 4 * js);
            ulonglong2 whz = *reinterpret_cast<const ulonglong2*>(WHs + k * 192 +  64 + 4 * js);
            ulonglong2 win = *reinterpret_cast<const ulonglong2*>(WIs + k * 192 + 128 + 4 * js);
            ulonglong2 whn = *reinterpret_cast<const ulonglong2*>(WHs + k * 192 + 128 + 4 * js);
            u64t ps[4] = {splat2(pv.x), splat2(pv.y), splat2(pv.z), splat2(pv.w)};
            u64t fs[4] = {splat2(fv.x), splat2(fv.y), splat2(fv.z), splat2(fv.w)};
            #pragma unroll
            for (int q = 0; q < 4; q++) {
                fma2(aR2[q][0], ps[q], wir.x);
                fma2(aR2[q][1], ps[q], wir.y);
                fma2(aR2[q][0], fs[q], whr.x);
                fma2(aR2[q][1], fs[q], whr.y);
                fma2(aZ2[q][0], ps[q], wiz.x);
                fma2(aZ2[q][1], ps[q], wiz.y);
                fma2(aZ2[q][0], fs[q], whz.x);
                fma2(aZ2[q][1], fs[q], whz.y);
                fma2(aI2[q][0], ps[q], win.x);
                fma2(aI2[q][1], ps[q], win.y);
                fma2(aH2[q][0], fs[q], whn.x);
                fma2(aH2[q][1], fs[q], whn.y);
            }
        }

        // --- GRU elementwise epilogue (scalar; unpack packed accumulators) ---
        {
            float4 birv = *reinterpret_cast<const float4*>(BIs +   0 + 4 * js);
            float4 bhrv = *reinterpret_cast<const float4*>(BHs +   0 + 4 * js);
            float4 bizv = *reinterpret_cast<const float4*>(BIs +  64 + 4 * js);
            float4 bhzv = *reinterpret_cast<const float4*>(BHs +  64 + 4 * js);
            float4 binv = *reinterpret_cast<const float4*>(BIs + 128 + 4 * js);
            float4 bhnv = *reinterpret_cast<const float4*>(BHs + 128 + 4 * js);
            const float brp[4] = {birv.x + bhrv.x, birv.y + bhrv.y, birv.z + bhrv.z, birv.w + bhrv.w};
            const float bzp[4] = {bizv.x + bhzv.x, bizv.y + bhzv.y, bizv.z + bhzv.z, bizv.w + bhzv.w};
            const float bip[4] = {binv.x, binv.y, binv.z, binv.w};
            const float bhp[4] = {bhnv.x, bhnv.y, bhnv.z, bhnv.w};

            float aR[4][4], aZ[4][4], aI[4][4], aH[4][4];
            #pragma unroll
            for (int q = 0; q < 4; q++) {
                float2 t;
                t = unpk(aR2[q][0]); aR[q][0] = t.x; aR[q][1] = t.y;
                t = unpk(aR2[q][1]); aR[q][2] = t.x; aR[q][3] = t.y;
                t = unpk(aZ2[q][0]); aZ[q][0] = t.x; aZ[q][1] = t.y;
                t = unpk(aZ2[q][1]); aZ[q][2] = t.x; aZ[q][3] = t.y;
                t = unpk(aI2[q][0]); aI[q][0] = t.x; aI[q][1] = t.y;
                t = unpk(aI2[q][1]); aI[q][2] = t.x; aI[q][3] = t.y;
                t = unpk(aH2[q][0]); aH[q][0] = t.x; aH[q][1] = t.y;
                t = unpk(aH2[q][1]); aH[q][2] = t.x; aH[q][3] = t.y;
            }

            #pragma unroll
            for (int p = 0; p < 4; p++) {
                float hq[4];
                #pragma unroll
                for (int q = 0; q < 4; q++) {
                    float r  = sigmoidf_(aR[q][p] + brp[p]);
                    float z  = sigmoidf_(aZ[q][p] + bzp[p]);
                    float nn = tanhf_(aI[q][p] + bip[p] + r * (aH[q][p] + bhp[p]));
                    float fv2 = XF[(4 * js + p) * PX + 4 * ns + q];
                    hq[q] = (1.0f - z) * nn + z * fv2;
                }
                // store H^T into XB (aliases dead agg1 tile)
                *reinterpret_cast<float4*>(XB + (4 * js + p) * PX + 4 * ns) =
                    make_float4(hq[0], hq[1], hq[2], hq[3]);
            }
        }
        __syncthreads();

        // --- GEMM3 (packed over node pairs): out[n][c], c = js ---
        u64t o2[2] = {0ULL, 0ULL};
        #pragma unroll 8
        for (int k = 0; k < 64; k++) {
            ulonglong2 h2 = *reinterpret_cast<const ulonglong2*>(XB + k * PX + 4 * ns);
            u64t ws = splat2(WOs[k * 16 + js]);
            fma2(o2[0], h2.x, ws);
            fma2(o2[1], h2.y, ws);
        }
        {
            float2 olo = unpk(o2[0]);
            float2 ohi = unpk(o2[1]);
            float o[4] = {olo.x, olo.y, ohi.x, ohi.y};
            float bo = BOs[js];
            #pragma unroll
            for (int q = 0; q < 4; q++) {
                int gn = base + 4 * ns + q;
                if (gn < NN) out[(size_t)gn * NC + js] = o[q] + bo;
            }
        }
    }
}

// ---------------------------------------------------------------------------
extern "C" void kernel_launch(void* const* d_in, const int* in_sizes, int n_in,
                              void* d_out, int out_size)
{
    const float* feat = (const float*)d_in[0];
    const int*   src  = (const int*)d_in[1];
    const int*   dst  = (const int*)d_in[2];
    const int*   et   = (const int*)d_in[3];
    const float* W0   = (const float*)d_in[4];
    const float* b0   = (const float*)d_in[5];
    const float* W1   = (const float*)d_in[6];
    const float* b1   = (const float*)d_in[7];
    const float* Wih  = (const float*)d_in[8];
    const float* Whh  = (const float*)d_in[9];
    const float* bih  = (const float*)d_in[10];
    const float* bhh  = (const float*)d_in[11];
    const float* Wout = (const float*)d_in[12];
    const float* bout = (const float*)d_in[13];
    float* out = (float*)d_out;

    void *p0, *p1, *p2, *p3;
    cudaGetSymbolAddress(&p0, g_agg0);
    cudaGetSymbolAddress(&p1, g_agg1);
    cudaGetSymbolAddress(&p2, g_cnt0);
    cudaGetSymbolAddress(&p3, g_cnt1);
    cudaMemsetAsync(p0, 0, sizeof(float) * (size_t)NN * HD);
    cudaMemsetAsync(p1, 0, sizeof(float) * (size_t)NN * HD);
    cudaMemsetAsync(p2, 0, sizeof(float) * NN);
    cudaMemsetAsync(p3, 0, sizeof(float) * NN);

    edge_kernel<<<(NE + 15) / 16, 256>>>(feat, src, dst, et);

    const int SMEM_BYTES = 47504 * 4;  // 190016 B
    cudaFuncSetAttribute(node_kernel,
                         cudaFuncAttributeMaxDynamicSharedMemorySize, SMEM_BYTES);
    node_kernel<<<148, 256, SMEM_BYTES>>>(feat, W0, b0, W1, b1,
                                          Wih, Whh, bih, bhh, Wout, bout, out);
}